// round 2
// baseline (speedup 1.0000x reference)
#include <cuda_runtime.h>
#include <cuda_bf16.h>
#include <cstdint>

#define MAX_NODES 50000
#define FEAT 128

// Ping-pong node-feature buffers (scratch; device globals per harness rules)
__device__ __align__(256) float g_bufA[MAX_NODES * FEAT];  // agg accumulator / gemm input
__device__ __align__(256) float g_bufB[MAX_NODES * FEAT];  // gemm output / next-layer features

// ---------------------------------------------------------------------------
// copy: dst = src  (initializes agg = x, the GIN self term)
// ---------------------------------------------------------------------------
__global__ void copy_kernel(const float* __restrict__ src, float* __restrict__ dst, int n4) {
    int i = blockIdx.x * blockDim.x + threadIdx.x;
    if (i < n4) ((float4*)dst)[i] = ((const float4*)src)[i];
}

// ---------------------------------------------------------------------------
// scatter: agg[dst[e]] += x[src[e]]   one warp per edge, red.global.add.v4.f32
// Edge indices are int32 (JAX x64 disabled -> int64 request degrades to int32).
// ---------------------------------------------------------------------------
__global__ void scatter_kernel(const float* __restrict__ x, float* __restrict__ agg,
                               const int* __restrict__ esrc,
                               const int* __restrict__ edst,
                               int n_edges) {
    int e = (blockIdx.x * blockDim.x + threadIdx.x) >> 5;
    int lane = threadIdx.x & 31;
    if (e >= n_edges) return;
    int s = __ldg(&esrc[e]);
    int d = __ldg(&edst[e]);
    float4 v = ((const float4*)(x + (size_t)s * FEAT))[lane];
    float* p = agg + (size_t)d * FEAT + lane * 4;
    asm volatile("red.global.add.v4.f32 [%0], {%1,%2,%3,%4};"
                 :: "l"(p), "f"(v.x), "f"(v.y), "f"(v.z), "f"(v.w) : "memory");
}

// ---------------------------------------------------------------------------
// gemm128: out[M,128] = act(A[M,128] @ W[128,128] + b)
// 256 threads, tile 32 rows x 128 cols, 4x4 micro-tile per thread.
// Dynamic smem: W (64KB) + A tile (16KB) + bias (512B)
// ---------------------------------------------------------------------------
__global__ void gemm128_kernel(const float* __restrict__ A, const float* __restrict__ W,
                               const float* __restrict__ bias, float* __restrict__ out,
                               int M, int relu) {
    extern __shared__ float smem[];
    float* Ws = smem;               // 128*128
    float* As = smem + 128 * 128;   // 32*128
    float* bs = As + 32 * 128;      // 128

    int tid = threadIdx.x;  // 0..255
    // Load W (4096 float4) and bias
    for (int i = tid; i < 128 * 128 / 4; i += 256)
        ((float4*)Ws)[i] = ((const float4*)W)[i];
    if (tid < 128) bs[tid] = bias[tid];
    __syncthreads();

    int tx = tid & 31;   // column group: cols tx*4 .. tx*4+3
    int ty = tid >> 5;   // row group:   rows ty*4 .. ty*4+3 (within 32-row tile)

    int row0 = blockIdx.x * 32;
    if (row0 >= M) return;

    // Load A tile: 32 rows x 128 floats = 1024 float4
    for (int i = tid; i < 1024; i += 256) {
        int r = i >> 5;          // row within tile
        int c = i & 31;          // float4 within row
        int row = row0 + r;
        float4 v = make_float4(0.f, 0.f, 0.f, 0.f);
        if (row < M) v = ((const float4*)(A + (size_t)row * FEAT))[c];
        ((float4*)As)[i] = v;
    }
    __syncthreads();

    float acc[4][4];
#pragma unroll
    for (int r = 0; r < 4; r++)
#pragma unroll
        for (int c = 0; c < 4; c++) acc[r][c] = 0.f;

#pragma unroll 4
    for (int k = 0; k < 128; k++) {
        float4 w = ((const float4*)(Ws + k * 128))[tx];
        float a0 = As[(ty * 4 + 0) * 128 + k];
        float a1 = As[(ty * 4 + 1) * 128 + k];
        float a2 = As[(ty * 4 + 2) * 128 + k];
        float a3 = As[(ty * 4 + 3) * 128 + k];
        acc[0][0] += a0 * w.x; acc[0][1] += a0 * w.y; acc[0][2] += a0 * w.z; acc[0][3] += a0 * w.w;
        acc[1][0] += a1 * w.x; acc[1][1] += a1 * w.y; acc[1][2] += a1 * w.z; acc[1][3] += a1 * w.w;
        acc[2][0] += a2 * w.x; acc[2][1] += a2 * w.y; acc[2][2] += a2 * w.z; acc[2][3] += a2 * w.w;
        acc[3][0] += a3 * w.x; acc[3][1] += a3 * w.y; acc[3][2] += a3 * w.z; acc[3][3] += a3 * w.w;
    }

#pragma unroll
    for (int r = 0; r < 4; r++) {
        int row = row0 + ty * 4 + r;
        if (row < M) {
            float4 o;
            o.x = acc[r][0] + bs[tx * 4 + 0];
            o.y = acc[r][1] + bs[tx * 4 + 1];
            o.z = acc[r][2] + bs[tx * 4 + 2];
            o.w = acc[r][3] + bs[tx * 4 + 3];
            if (relu) {
                o.x = fmaxf(o.x, 0.f); o.y = fmaxf(o.y, 0.f);
                o.z = fmaxf(o.z, 0.f); o.w = fmaxf(o.w, 0.f);
            }
            ((float4*)(out + (size_t)row * FEAT))[tx] = o;
        }
    }
}

// ---------------------------------------------------------------------------
// gemm2: out[M,2] = A[M,128] @ W3[128,2] + b3   (one warp per row)
// ---------------------------------------------------------------------------
__global__ void gemm2_kernel(const float* __restrict__ A, const float* __restrict__ W3,
                             const float* __restrict__ b3, float* __restrict__ out, int M) {
    int row = (blockIdx.x * blockDim.x + threadIdx.x) >> 5;
    int lane = threadIdx.x & 31;
    if (row >= M) return;
    float s0 = 0.f, s1 = 0.f;
#pragma unroll
    for (int j = 0; j < 4; j++) {
        int k = lane + 32 * j;
        float a = A[(size_t)row * FEAT + k];
        s0 += a * __ldg(&W3[k * 2 + 0]);
        s1 += a * __ldg(&W3[k * 2 + 1]);
    }
#pragma unroll
    for (int o = 16; o; o >>= 1) {
        s0 += __shfl_xor_sync(0xFFFFFFFFu, s0, o);
        s1 += __shfl_xor_sync(0xFFFFFFFFu, s1, o);
    }
    if (lane == 0) {
        out[(size_t)row * 2 + 0] = s0 + __ldg(&b3[0]);
        out[(size_t)row * 2 + 1] = s1 + __ldg(&b3[1]);
    }
}

// ---------------------------------------------------------------------------
extern "C" void kernel_launch(void* const* d_in, const int* in_sizes, int n_in,
                              void* d_out, int out_size) {
    const float* x    = (const float*)d_in[0];
    const int*   ei   = (const int*)d_in[1];   // [2, E] int32 (JAX x64 off)
    const float* W1   = (const float*)d_in[2];
    const float* b1   = (const float*)d_in[3];
    const float* W2   = (const float*)d_in[4];
    const float* b2   = (const float*)d_in[5];
    const float* W3   = (const float*)d_in[6];
    const float* b3   = (const float*)d_in[7];
    float*       out  = (float*)d_out;

    int n_nodes = in_sizes[0] / FEAT;
    int n_edges = in_sizes[1] / 2;
    const int* esrc = ei;
    const int* edst = ei + n_edges;

    float* bufA; cudaGetSymbolAddress((void**)&bufA, g_bufA);
    float* bufB; cudaGetSymbolAddress((void**)&bufB, g_bufB);

    const int gemm_smem = (128 * 128 + 32 * 128 + 128) * (int)sizeof(float);
    cudaFuncSetAttribute(gemm128_kernel, cudaFuncAttributeMaxDynamicSharedMemorySize, gemm_smem);

    int n4 = n_nodes * FEAT / 4;
    int copy_blocks    = (n4 + 255) / 256;
    int scatter_blocks = (n_edges + 7) / 8;          // 8 warps per 256-thread block
    int gemm_blocks    = (n_nodes + 31) / 32;
    int g2_blocks      = (n_nodes * 32 + 255) / 256; // one warp per row

    // ---- Layer 1 ----
    copy_kernel<<<copy_blocks, 256>>>(x, bufA, n4);
    scatter_kernel<<<scatter_blocks, 256>>>(x, bufA, esrc, edst, n_edges);
    gemm128_kernel<<<gemm_blocks, 256, gemm_smem>>>(bufA, W1, b1, bufB, n_nodes, 1);

    // ---- Layer 2 ----
    copy_kernel<<<copy_blocks, 256>>>(bufB, bufA, n4);
    scatter_kernel<<<scatter_blocks, 256>>>(bufB, bufA, esrc, edst, n_edges);
    gemm128_kernel<<<gemm_blocks, 256, gemm_smem>>>(bufA, W2, b2, bufB, n_nodes, 1);

    // ---- Layer 3 ----
    copy_kernel<<<copy_blocks, 256>>>(bufB, bufA, n4);
    scatter_kernel<<<scatter_blocks, 256>>>(bufB, bufA, esrc, edst, n_edges);
    gemm2_kernel<<<g2_blocks, 256>>>(bufA, W3, b3, out, n_nodes);
}

// round 3
// speedup vs baseline: 1.8376x; 1.8376x over previous
#include <cuda_runtime.h>
#include <cuda_bf16.h>
#include <cstdint>

#define MAX_NODES 50000
#define MAX_EDGES 1600000
#define FEAT 128

// Scratch (device globals per harness rules)
__device__ __align__(256) float g_bufA[MAX_NODES * FEAT];
__device__ __align__(256) float g_bufB[MAX_NODES * FEAT];
__device__ __align__(256) float g_p[MAX_NODES * 2];
__device__ int g_off[MAX_NODES + 1];
__device__ int g_cursor[MAX_NODES];
__device__ int g_col[MAX_EDGES];

// ---------------------------------------------------------------------------
// CSR build: histogram of dst
// ---------------------------------------------------------------------------
__global__ void hist_kernel(const int* __restrict__ edst, int* __restrict__ deg, int n_edges) {
    int i = blockIdx.x * blockDim.x + threadIdx.x;
    if (i < n_edges) atomicAdd(&deg[__ldg(&edst[i])], 1);
}

// Single-block exclusive scan over n counters -> off[0..n], cursor copy.
// deg is read from 'cursor' slot? No: deg lives in g_cursor? We store hist in
// g_cursor first, scan into g_off, and reset g_cursor to the exclusive offsets.
__global__ void scan_kernel(int* __restrict__ deg /*in: counts*/, int* __restrict__ off,
                            int* __restrict__ cursor, int n) {
    __shared__ int sm[1024];
    __shared__ int carry;
    if (threadIdx.x == 0) carry = 0;
    __syncthreads();
    for (int base = 0; base < n; base += 1024) {
        int i = base + threadIdx.x;
        int v = (i < n) ? deg[i] : 0;
        sm[threadIdx.x] = v;
        __syncthreads();
#pragma unroll
        for (int o = 1; o < 1024; o <<= 1) {
            int t = (threadIdx.x >= o) ? sm[threadIdx.x - o] : 0;
            __syncthreads();
            sm[threadIdx.x] += t;
            __syncthreads();
        }
        int excl = sm[threadIdx.x] - v;
        if (i < n) { off[i] = carry + excl; cursor[i] = carry + excl; }
        __syncthreads();
        if (threadIdx.x == 1023) carry += sm[1023];
        __syncthreads();
    }
    if (threadIdx.x == 0) off[n] = carry;
}

// Fill CSR column (src) array
__global__ void fill_kernel(const int* __restrict__ esrc, const int* __restrict__ edst,
                            int* __restrict__ cursor, int* __restrict__ col, int n_edges) {
    int i = blockIdx.x * blockDim.x + threadIdx.x;
    if (i < n_edges) {
        int d = __ldg(&edst[i]);
        int pos = atomicAdd(&cursor[d], 1);
        col[pos] = __ldg(&esrc[i]);
    }
}

// ---------------------------------------------------------------------------
// gather128: agg[i] = x[i] + sum_{j in N(i)} x[j]   (warp per node, float4/lane)
// ---------------------------------------------------------------------------
__global__ void gather128_kernel(const float* __restrict__ x, float* __restrict__ agg,
                                 const int* __restrict__ off, const int* __restrict__ col,
                                 int n_nodes) {
    int node = (blockIdx.x * blockDim.x + threadIdx.x) >> 5;
    int lane = threadIdx.x & 31;
    if (node >= n_nodes) return;
    int k  = __ldg(&off[node]);
    int k1 = __ldg(&off[node + 1]);
    const float4* x4 = (const float4*)x;
    float4 acc = x4[(size_t)node * 32 + lane];   // self term (GIN eps=0)
    int nxt = (k < k1) ? __ldg(&col[k]) : 0;
    while (k < k1) {
        int s = nxt;
        k++;
        if (k < k1) nxt = __ldg(&col[k]);
        float4 v = x4[(size_t)s * 32 + lane];
        acc.x += v.x; acc.y += v.y; acc.z += v.z; acc.w += v.w;
    }
    ((float4*)agg)[(size_t)node * 32 + lane] = acc;
}

// ---------------------------------------------------------------------------
// gemm128: out[M,128] = relu(A[M,128] @ W[128,128] + b)
// ---------------------------------------------------------------------------
__global__ void gemm128_kernel(const float* __restrict__ A, const float* __restrict__ W,
                               const float* __restrict__ bias, float* __restrict__ out,
                               int M) {
    extern __shared__ float smem[];
    float* Ws = smem;               // 128*128
    float* As = smem + 128 * 128;   // 32*128
    float* bs = As + 32 * 128;      // 128

    int tid = threadIdx.x;  // 0..255
    for (int i = tid; i < 128 * 128 / 4; i += 256)
        ((float4*)Ws)[i] = ((const float4*)W)[i];
    if (tid < 128) bs[tid] = bias[tid];

    int tx = tid & 31;
    int ty = tid >> 5;
    int row0 = blockIdx.x * 32;

    for (int i = tid; i < 1024; i += 256) {
        int r = i >> 5;
        int c = i & 31;
        int row = row0 + r;
        float4 v = make_float4(0.f, 0.f, 0.f, 0.f);
        if (row < M) v = ((const float4*)(A + (size_t)row * FEAT))[c];
        ((float4*)As)[i] = v;
    }
    __syncthreads();

    float acc[4][4];
#pragma unroll
    for (int r = 0; r < 4; r++)
#pragma unroll
        for (int c = 0; c < 4; c++) acc[r][c] = 0.f;

#pragma unroll 4
    for (int k = 0; k < 128; k++) {
        float4 w = ((const float4*)(Ws + k * 128))[tx];
        float a0 = As[(ty * 4 + 0) * 128 + k];
        float a1 = As[(ty * 4 + 1) * 128 + k];
        float a2 = As[(ty * 4 + 2) * 128 + k];
        float a3 = As[(ty * 4 + 3) * 128 + k];
        acc[0][0] += a0 * w.x; acc[0][1] += a0 * w.y; acc[0][2] += a0 * w.z; acc[0][3] += a0 * w.w;
        acc[1][0] += a1 * w.x; acc[1][1] += a1 * w.y; acc[1][2] += a1 * w.z; acc[1][3] += a1 * w.w;
        acc[2][0] += a2 * w.x; acc[2][1] += a2 * w.y; acc[2][2] += a2 * w.z; acc[2][3] += a2 * w.w;
        acc[3][0] += a3 * w.x; acc[3][1] += a3 * w.y; acc[3][2] += a3 * w.z; acc[3][3] += a3 * w.w;
    }

#pragma unroll
    for (int r = 0; r < 4; r++) {
        int row = row0 + ty * 4 + r;
        if (row < M) {
            float4 o;
            o.x = fmaxf(acc[r][0] + bs[tx * 4 + 0], 0.f);
            o.y = fmaxf(acc[r][1] + bs[tx * 4 + 1], 0.f);
            o.z = fmaxf(acc[r][2] + bs[tx * 4 + 2], 0.f);
            o.w = fmaxf(acc[r][3] + bs[tx * 4 + 3], 0.f);
            ((float4*)(out + (size_t)row * FEAT))[tx] = o;
        }
    }
}

// ---------------------------------------------------------------------------
// gemmP: p[M,2] = A[M,128] @ W3[128,2]   (NO bias; one warp per row)
// ---------------------------------------------------------------------------
__global__ void gemmP_kernel(const float* __restrict__ A, const float* __restrict__ W3,
                             float* __restrict__ p, int M) {
    int row = (blockIdx.x * blockDim.x + threadIdx.x) >> 5;
    int lane = threadIdx.x & 31;
    if (row >= M) return;
    float s0 = 0.f, s1 = 0.f;
#pragma unroll
    for (int j = 0; j < 4; j++) {
        int k = lane + 32 * j;
        float a = A[(size_t)row * FEAT + k];
        s0 += a * __ldg(&W3[k * 2 + 0]);
        s1 += a * __ldg(&W3[k * 2 + 1]);
    }
#pragma unroll
    for (int o = 16; o; o >>= 1) {
        s0 += __shfl_xor_sync(0xFFFFFFFFu, s0, o);
        s1 += __shfl_xor_sync(0xFFFFFFFFu, s1, o);
    }
    if (lane == 0) {
        p[(size_t)row * 2 + 0] = s0;
        p[(size_t)row * 2 + 1] = s1;
    }
}

// ---------------------------------------------------------------------------
// gatherP: out[i] = p[i] + sum_{j in N(i)} p[j] + b3   (2-wide; warp per node)
// ---------------------------------------------------------------------------
__global__ void gatherP_kernel(const float* __restrict__ p, float* __restrict__ out,
                               const int* __restrict__ off, const int* __restrict__ col,
                               const float* __restrict__ b3, int n_nodes) {
    int node = (blockIdx.x * blockDim.x + threadIdx.x) >> 5;
    int lane = threadIdx.x & 31;
    if (node >= n_nodes) return;
    int k0 = __ldg(&off[node]);
    int k1 = __ldg(&off[node + 1]);
    float a0 = 0.f, a1 = 0.f;
    const float2* p2 = (const float2*)p;
    for (int k = k0 + lane; k < k1; k += 32) {
        int s = __ldg(&col[k]);
        float2 v = p2[s];
        a0 += v.x; a1 += v.y;
    }
#pragma unroll
    for (int o = 16; o; o >>= 1) {
        a0 += __shfl_xor_sync(0xFFFFFFFFu, a0, o);
        a1 += __shfl_xor_sync(0xFFFFFFFFu, a1, o);
    }
    if (lane == 0) {
        float2 self = p2[node];
        out[(size_t)node * 2 + 0] = self.x + a0 + __ldg(&b3[0]);
        out[(size_t)node * 2 + 1] = self.y + a1 + __ldg(&b3[1]);
    }
}

// ---------------------------------------------------------------------------
extern "C" void kernel_launch(void* const* d_in, const int* in_sizes, int n_in,
                              void* d_out, int out_size) {
    const float* x    = (const float*)d_in[0];
    const int*   ei   = (const int*)d_in[1];   // [2, E] int32
    const float* W1   = (const float*)d_in[2];
    const float* b1   = (const float*)d_in[3];
    const float* W2   = (const float*)d_in[4];
    const float* b2   = (const float*)d_in[5];
    const float* W3   = (const float*)d_in[6];
    const float* b3   = (const float*)d_in[7];
    float*       out  = (float*)d_out;

    int n_nodes = in_sizes[0] / FEAT;
    int n_edges = in_sizes[1] / 2;
    const int* esrc = ei;
    const int* edst = ei + n_edges;

    float* bufA;   cudaGetSymbolAddress((void**)&bufA,   g_bufA);
    float* bufB;   cudaGetSymbolAddress((void**)&bufB,   g_bufB);
    float* pbuf;   cudaGetSymbolAddress((void**)&pbuf,   g_p);
    int*   off;    cudaGetSymbolAddress((void**)&off,    g_off);
    int*   cursor; cudaGetSymbolAddress((void**)&cursor, g_cursor);
    int*   col;    cudaGetSymbolAddress((void**)&col,    g_col);

    const int gemm_smem = (128 * 128 + 32 * 128 + 128) * (int)sizeof(float);
    cudaFuncSetAttribute(gemm128_kernel, cudaFuncAttributeMaxDynamicSharedMemorySize, gemm_smem);

    int edge_blocks = (n_edges + 255) / 256;
    int node_warp_blocks = (n_nodes * 32 + 255) / 256;  // warp per node
    int gemm_blocks = (n_nodes + 31) / 32;

    // ---- CSR build (histogram into cursor, scan -> off + cursor, fill col) ----
    cudaMemsetAsync(cursor, 0, n_nodes * sizeof(int));
    hist_kernel<<<edge_blocks, 256>>>(edst, cursor, n_edges);
    scan_kernel<<<1, 1024>>>(cursor, off, cursor, n_nodes);
    // NOTE: scan reads counts from cursor and overwrites cursor with offsets:
    // safe because each index is read before being written within the same thread.
    fill_kernel<<<edge_blocks, 256>>>(esrc, edst, cursor, col, n_edges);

    // ---- Layer 1: agg+self, GEMM+ReLU ----
    gather128_kernel<<<node_warp_blocks, 256>>>(x, bufA, off, col, n_nodes);
    gemm128_kernel<<<gemm_blocks, 256, gemm_smem>>>(bufA, W1, b1, bufB, n_nodes);

    // ---- Layer 2 ----
    gather128_kernel<<<node_warp_blocks, 256>>>(bufB, bufA, off, col, n_nodes);
    gemm128_kernel<<<gemm_blocks, 256, gemm_smem>>>(bufA, W2, b2, bufB, n_nodes);

    // ---- Layer 3 (project to 2 dims FIRST, then aggregate 2-wide) ----
    gemmP_kernel<<<node_warp_blocks, 256>>>(bufB, W3, pbuf, n_nodes);
    gatherP_kernel<<<node_warp_blocks, 256>>>(pbuf, out, off, col, b3, n_nodes);
}

// round 5
// speedup vs baseline: 2.3713x; 1.2904x over previous
#include <cuda_runtime.h>
#include <cuda_bf16.h>
#include <cstdint>

#define MAX_NODES 50000
#define MAX_EDGES 1600000
#define FEAT 128
#define PAD 133   // smem row pitch (floats): odd*? -> (5n+k) mod 32 conflict-free

// Scratch (device globals per harness rules)
__device__ __align__(256) float g_bufA[MAX_NODES * FEAT];
__device__ __align__(256) float g_bufB[MAX_NODES * FEAT];
__device__ __align__(256) float g_p[MAX_NODES * 2];
__device__ int g_off[MAX_NODES + 1];
__device__ int g_cursor[MAX_NODES];
__device__ int g_col[MAX_EDGES];

// ---------------------------------------------------------------------------
// CSR build
// ---------------------------------------------------------------------------
__global__ void hist_kernel(const int* __restrict__ edst, int* __restrict__ deg, int n_edges) {
    int i = blockIdx.x * blockDim.x + threadIdx.x;
    if (i < n_edges) atomicAdd(&deg[__ldg(&edst[i])], 1);
}

// warp-shuffle single-block exclusive scan: counts -> off[0..n] and cursor
__global__ void scan_kernel(const int* __restrict__ counts, int* __restrict__ off,
                            int* __restrict__ cursor, int n) {
    __shared__ int wtot[32];
    __shared__ int carry_s;
    __shared__ int btotal;
    int tid = threadIdx.x, lane = tid & 31, wid = tid >> 5;
    if (tid == 0) carry_s = 0;
    __syncthreads();
    for (int base = 0; base < n; base += 1024) {
        int i = base + tid;
        int v = (i < n) ? counts[i] : 0;
        int incl = v;
#pragma unroll
        for (int o = 1; o < 32; o <<= 1) {
            int t = __shfl_up_sync(0xFFFFFFFFu, incl, o);
            if (lane >= o) incl += t;
        }
        if (lane == 31) wtot[wid] = incl;
        __syncthreads();
        if (wid == 0) {
            int w = wtot[lane];
            int wi = w;
#pragma unroll
            for (int o = 1; o < 32; o <<= 1) {
                int t = __shfl_up_sync(0xFFFFFFFFu, wi, o);
                if (lane >= o) wi += t;
            }
            wtot[lane] = wi - w;
            if (lane == 31) btotal = wi;
        }
        __syncthreads();
        int excl = carry_s + wtot[wid] + incl - v;
        if (i < n) { off[i] = excl; cursor[i] = excl; }
        __syncthreads();
        if (tid == 0) carry_s += btotal;
        __syncthreads();
    }
    if (threadIdx.x == 0) off[n] = carry_s;
}

__global__ void fill_kernel(const int* __restrict__ esrc, const int* __restrict__ edst,
                            int* __restrict__ cursor, int* __restrict__ col, int n_edges) {
    int i = blockIdx.x * blockDim.x + threadIdx.x;
    if (i < n_edges) {
        int d = __ldg(&edst[i]);
        int pos = atomicAdd(&cursor[d], 1);
        col[pos] = __ldg(&esrc[i]);
    }
}

// ---------------------------------------------------------------------------
// gather128: agg[i] = x[i] + sum_{j in N(i)} x[j]   (warp per node)
// ---------------------------------------------------------------------------
__global__ void gather128_kernel(const float* __restrict__ x, float* __restrict__ agg,
                                 const int* __restrict__ off, const int* __restrict__ col,
                                 int n_nodes) {
    int node = (blockIdx.x * blockDim.x + threadIdx.x) >> 5;
    int lane = threadIdx.x & 31;
    if (node >= n_nodes) return;
    int k  = __ldg(&off[node]);
    int k1 = __ldg(&off[node + 1]);
    const float4* x4 = (const float4*)x;
    float4 acc = x4[(size_t)node * 32 + lane];
    int nxt = (k < k1) ? __ldg(&col[k]) : 0;
    while (k < k1) {
        int s = nxt;
        k++;
        if (k < k1) nxt = __ldg(&col[k]);
        float4 v = x4[(size_t)s * 32 + lane];
        acc.x += v.x; acc.y += v.y; acc.z += v.z; acc.w += v.w;
    }
    ((float4*)agg)[(size_t)node * 32 + lane] = acc;
}

// ---------------------------------------------------------------------------
// mma_gemm: out[M,128] = relu(A[M,128] @ W[128,128] + b)
// mma.sync.m16n8k8 tf32. CTA = 128 rows, 256 threads (8 warps x 16-row tiles).
// smem: As[128][PAD] (tf32 bits), Ws[n][k] = tf32(W[k][n]) [128][PAD], bias.
// ---------------------------------------------------------------------------
#define MMA_SMEM ((2 * 128 * PAD + 128) * 4)

__device__ __forceinline__ uint32_t f2tf32(float f) {
    uint32_t r;
    asm("cvt.rn.tf32.f32 %0, %1;" : "=r"(r) : "f"(f));
    return r;
}

__global__ void __launch_bounds__(256, 1) mma_gemm_kernel(
    const float* __restrict__ A, const float* __restrict__ W,
    const float* __restrict__ bias, float* __restrict__ out, int M) {
    extern __shared__ float smf[];
    uint32_t* As = (uint32_t*)smf;                 // 128*PAD tf32
    uint32_t* Ws = (uint32_t*)(smf + 128 * PAD);   // 128*PAD tf32 (transposed)
    float*    bs = smf + 2 * 128 * PAD;            // 128

    int tid = threadIdx.x;
    int lane = tid & 31, wid = tid >> 5;
    int row0 = blockIdx.x * 128;

    if (tid < 128) bs[tid] = bias[tid];

    // Stage Wt: Ws[n][k] = tf32(W[k][n]); coalesced 128B reads, conflict-free writes
    for (int k = wid; k < 128; k += 8) {
#pragma unroll
        for (int nb = 0; nb < 128; nb += 32) {
            int n = nb + lane;
            Ws[n * PAD + k] = f2tf32(__ldg(&W[k * 128 + n]));
        }
    }
    // Stage A rows (zero-padded past M)
    for (int r = wid; r < 128; r += 8) {
        int row = row0 + r;
        if (row < M) {
#pragma unroll
            for (int cb = 0; cb < 128; cb += 32)
                As[r * PAD + cb + lane] = f2tf32(A[(size_t)row * 128 + cb + lane]);
        } else {
#pragma unroll
            for (int cb = 0; cb < 128; cb += 32)
                As[r * PAD + cb + lane] = 0u;
        }
    }
    __syncthreads();

    int g = lane >> 2;   // 0..7
    int i = lane & 3;    // 0..3
    int wrow = wid * 16;

    // A fragments: 16 k-tiles x 4 regs
    uint32_t a[16][4];
#pragma unroll
    for (int kt = 0; kt < 16; kt++) {
        int base = (wrow + g) * PAD + kt * 8 + i;
        a[kt][0] = As[base];
        a[kt][1] = As[base + 8 * PAD];
        a[kt][2] = As[base + 4];
        a[kt][3] = As[base + 8 * PAD + 4];
    }

    int r0 = row0 + wrow + g;
    int r1 = r0 + 8;
#pragma unroll
    for (int nt = 0; nt < 16; nt++) {
        float c0 = 0.f, c1 = 0.f, c2 = 0.f, c3 = 0.f;
        int brow = (nt * 8 + g) * PAD;
#pragma unroll
        for (int kt = 0; kt < 16; kt++) {
            uint32_t b0 = Ws[brow + kt * 8 + i];
            uint32_t b1 = Ws[brow + kt * 8 + i + 4];
            asm volatile(
                "mma.sync.aligned.m16n8k8.row.col.f32.tf32.tf32.f32 "
                "{%0,%1,%2,%3}, {%4,%5,%6,%7}, {%8,%9}, {%0,%1,%2,%3};"
                : "+f"(c0), "+f"(c1), "+f"(c2), "+f"(c3)
                : "r"(a[kt][0]), "r"(a[kt][1]), "r"(a[kt][2]), "r"(a[kt][3]),
                  "r"(b0), "r"(b1));
        }
        int cb = nt * 8 + 2 * i;
        float bx = bs[cb], by = bs[cb + 1];
        if (r0 < M) {
            float2 o;
            o.x = fmaxf(c0 + bx, 0.f);
            o.y = fmaxf(c1 + by, 0.f);
            *(float2*)(out + (size_t)r0 * 128 + cb) = o;
        }
        if (r1 < M) {
            float2 o;
            o.x = fmaxf(c2 + bx, 0.f);
            o.y = fmaxf(c3 + by, 0.f);
            *(float2*)(out + (size_t)r1 * 128 + cb) = o;
        }
    }
}

// ---------------------------------------------------------------------------
// gemmP: p[M,2] = A[M,128] @ W3[128,2]   (no bias; warp per row)
// ---------------------------------------------------------------------------
__global__ void gemmP_kernel(const float* __restrict__ A, const float* __restrict__ W3,
                             float* __restrict__ p, int M) {
    int row = (blockIdx.x * blockDim.x + threadIdx.x) >> 5;
    int lane = threadIdx.x & 31;
    if (row >= M) return;
    float s0 = 0.f, s1 = 0.f;
#pragma unroll
    for (int j = 0; j < 4; j++) {
        int k = lane + 32 * j;
        float a = A[(size_t)row * FEAT + k];
        s0 += a * __ldg(&W3[k * 2 + 0]);
        s1 += a * __ldg(&W3[k * 2 + 1]);
    }
#pragma unroll
    for (int o = 16; o; o >>= 1) {
        s0 += __shfl_xor_sync(0xFFFFFFFFu, s0, o);
        s1 += __shfl_xor_sync(0xFFFFFFFFu, s1, o);
    }
    if (lane == 0) {
        p[(size_t)row * 2 + 0] = s0;
        p[(size_t)row * 2 + 1] = s1;
    }
}

// ---------------------------------------------------------------------------
// gatherP: out[i] = p[i] + sum_{j in N(i)} p[j] + b3
// ---------------------------------------------------------------------------
__global__ void gatherP_kernel(const float* __restrict__ p, float* __restrict__ out,
                               const int* __restrict__ off, const int* __restrict__ col,
                               const float* __restrict__ b3, int n_nodes) {
    int node = (blockIdx.x * blockDim.x + threadIdx.x) >> 5;
    int lane = threadIdx.x & 31;
    if (node >= n_nodes) return;
    int k0 = __ldg(&off[node]);
    int k1 = __ldg(&off[node + 1]);
    float a0 = 0.f, a1 = 0.f;
    const float2* p2 = (const float2*)p;
    for (int k = k0 + lane; k < k1; k += 32) {
        int s = __ldg(&col[k]);
        float2 v = p2[s];
        a0 += v.x; a1 += v.y;
    }
#pragma unroll
    for (int o = 16; o; o >>= 1) {
        a0 += __shfl_xor_sync(0xFFFFFFFFu, a0, o);
        a1 += __shfl_xor_sync(0xFFFFFFFFu, a1, o);
    }
    if (lane == 0) {
        float2 self = p2[node];
        out[(size_t)node * 2 + 0] = self.x + a0 + __ldg(&b3[0]);
        out[(size_t)node * 2 + 1] = self.y + a1 + __ldg(&b3[1]);
    }
}

// ---------------------------------------------------------------------------
extern "C" void kernel_launch(void* const* d_in, const int* in_sizes, int n_in,
                              void* d_out, int out_size) {
    const float* x    = (const float*)d_in[0];
    const int*   ei   = (const int*)d_in[1];   // [2, E] int32
    const float* W1   = (const float*)d_in[2];
    const float* b1   = (const float*)d_in[3];
    const float* W2   = (const float*)d_in[4];
    const float* b2   = (const float*)d_in[5];
    const float* W3   = (const float*)d_in[6];
    const float* b3   = (const float*)d_in[7];
    float*       out  = (float*)d_out;

    int n_nodes = in_sizes[0] / FEAT;
    int n_edges = in_sizes[1] / 2;
    const int* esrc = ei;
    const int* edst = ei + n_edges;

    float* bufA;   cudaGetSymbolAddress((void**)&bufA,   g_bufA);
    float* bufB;   cudaGetSymbolAddress((void**)&bufB,   g_bufB);
    float* pbuf;   cudaGetSymbolAddress((void**)&pbuf,   g_p);
    int*   off;    cudaGetSymbolAddress((void**)&off,    g_off);
    int*   cursor; cudaGetSymbolAddress((void**)&cursor, g_cursor);
    int*   col;    cudaGetSymbolAddress((void**)&col,    g_col);

    cudaFuncSetAttribute(mma_gemm_kernel, cudaFuncAttributeMaxDynamicSharedMemorySize, MMA_SMEM);

    int edge_blocks = (n_edges + 255) / 256;
    int node_warp_blocks = (n_nodes * 32 + 255) / 256;
    int tc_blocks = (n_nodes + 127) / 128;

    // ---- CSR build ----
    cudaMemsetAsync(cursor, 0, n_nodes * sizeof(int));
    hist_kernel<<<edge_blocks, 256>>>(edst, cursor, n_edges);
    scan_kernel<<<1, 1024>>>(cursor, off, cursor, n_nodes);
    fill_kernel<<<edge_blocks, 256>>>(esrc, edst, cursor, col, n_edges);

    // ---- Layer 1 ----
    gather128_kernel<<<node_warp_blocks, 256>>>(x, bufA, off, col, n_nodes);
    mma_gemm_kernel<<<tc_blocks, 256, MMA_SMEM>>>(bufA, W1, b1, bufB, n_nodes);

    // ---- Layer 2 ----
    gather128_kernel<<<node_warp_blocks, 256>>>(bufB, bufA, off, col, n_nodes);
    mma_gemm_kernel<<<tc_blocks, 256, MMA_SMEM>>>(bufA, W2, b2, bufB, n_nodes);

    // ---- Layer 3 (project to 2-wide first, aggregate after) ----
    gemmP_kernel<<<node_warp_blocks, 256>>>(bufB, W3, pbuf, n_nodes);
    gatherP_kernel<<<node_warp_blocks, 256>>>(pbuf, out, off, col, b3, n_nodes);
}

// round 6
// speedup vs baseline: 3.0570x; 1.2891x over previous
#include <cuda_runtime.h>
#include <cuda_bf16.h>
#include <cstdint>

#define MAX_NODES 50000
#define MAX_EDGES 1600000
#define FEAT 128
#define PAD 132   // Ws pitch (floats): frag-load bank = g*4+i -> conflict-free

// Scratch (device globals per harness rules)
__device__ __align__(256) float g_bufA[MAX_NODES * FEAT];
__device__ __align__(256) float g_bufB[MAX_NODES * FEAT];
__device__ __align__(256) float g_p[MAX_NODES * 2];
__device__ int g_off[MAX_NODES + 1];
__device__ int g_cursor[MAX_NODES];
__device__ int g_col[MAX_EDGES];
__device__ int g_bsum[64];

// ---------------------------------------------------------------------------
// CSR build
// ---------------------------------------------------------------------------
__global__ void hist_kernel(const int* __restrict__ edst, int* __restrict__ deg, int n_edges) {
    int i = blockIdx.x * blockDim.x + threadIdx.x;
    if (i < n_edges) atomicAdd(&deg[__ldg(&edst[i])], 1);
}

// Per-block exclusive scan of 1024 counts; writes local-exclusive into off, block sum into bsum
__global__ void scan_block_kernel(const int* __restrict__ counts, int* __restrict__ off,
                                  int* __restrict__ bsum, int n) {
    __shared__ int wtot[32];
    int tid = threadIdx.x, lane = tid & 31, wid = tid >> 5;
    int i = blockIdx.x * 1024 + tid;
    int v = (i < n) ? counts[i] : 0;
    int incl = v;
#pragma unroll
    for (int o = 1; o < 32; o <<= 1) {
        int t = __shfl_up_sync(0xFFFFFFFFu, incl, o);
        if (lane >= o) incl += t;
    }
    if (lane == 31) wtot[wid] = incl;
    __syncthreads();
    if (wid == 0) {
        int w = wtot[lane];
        int wi = w;
#pragma unroll
        for (int o = 1; o < 32; o <<= 1) {
            int t = __shfl_up_sync(0xFFFFFFFFu, wi, o);
            if (lane >= o) wi += t;
        }
        wtot[lane] = wi - w;
        if (lane == 31) bsum[blockIdx.x] = wi;
    }
    __syncthreads();
    if (i < n) off[i] = wtot[wid] + incl - v;
}

// Single-block exclusive scan of block sums (nb <= 1024); writes grand total to off[n]
__global__ void scan_tops_kernel(int* __restrict__ bsum, int nb, int* __restrict__ off, int n) {
    __shared__ int wtot[32];
    __shared__ int btotal;
    int tid = threadIdx.x, lane = tid & 31, wid = tid >> 5;
    int v = (tid < nb) ? bsum[tid] : 0;
    int incl = v;
#pragma unroll
    for (int o = 1; o < 32; o <<= 1) {
        int t = __shfl_up_sync(0xFFFFFFFFu, incl, o);
        if (lane >= o) incl += t;
    }
    if (lane == 31) wtot[wid] = incl;
    __syncthreads();
    if (wid == 0) {
        int w = wtot[lane];
        int wi = w;
#pragma unroll
        for (int o = 1; o < 32; o <<= 1) {
            int t = __shfl_up_sync(0xFFFFFFFFu, wi, o);
            if (lane >= o) wi += t;
        }
        wtot[lane] = wi - w;
        if (lane == 31) btotal = wi;
    }
    __syncthreads();
    if (tid < nb) bsum[tid] = wtot[wid] + incl - v;
    if (tid == 0) off[n] = btotal;
}

// off[i] += bsum[block]; cursor[i] = off[i]
__global__ void scan_add_kernel(int* __restrict__ off, const int* __restrict__ bsum,
                                int* __restrict__ cursor, int n) {
    int i = blockIdx.x * 1024 + threadIdx.x;
    if (i < n) {
        int v = off[i] + bsum[blockIdx.x];
        off[i] = v;
        cursor[i] = v;
    }
}

__global__ void fill_kernel(const int* __restrict__ esrc, const int* __restrict__ edst,
                            int* __restrict__ cursor, int* __restrict__ col, int n_edges) {
    int i = blockIdx.x * blockDim.x + threadIdx.x;
    if (i < n_edges) {
        int d = __ldg(&edst[i]);
        int pos = atomicAdd(&cursor[d], 1);
        col[pos] = __ldg(&esrc[i]);
    }
}

// ---------------------------------------------------------------------------
// gather128: agg[i] = x[i] + sum_{j in N(i)} x[j]   (warp per node)
// ---------------------------------------------------------------------------
__global__ void gather128_kernel(const float* __restrict__ x, float* __restrict__ agg,
                                 const int* __restrict__ off, const int* __restrict__ col,
                                 int n_nodes) {
    int node = (blockIdx.x * blockDim.x + threadIdx.x) >> 5;
    int lane = threadIdx.x & 31;
    if (node >= n_nodes) return;
    int k  = __ldg(&off[node]);
    int k1 = __ldg(&off[node + 1]);
    const float4* x4 = (const float4*)x;
    float4 acc = x4[(size_t)node * 32 + lane];
    int nxt = (k < k1) ? __ldg(&col[k]) : 0;
    while (k < k1) {
        int s = nxt;
        k++;
        if (k < k1) nxt = __ldg(&col[k]);
        float4 v = x4[(size_t)s * 32 + lane];
        acc.x += v.x; acc.y += v.y; acc.z += v.z; acc.w += v.w;
    }
    ((float4*)agg)[(size_t)node * 32 + lane] = acc;
}

// ---------------------------------------------------------------------------
// mma_gemm: out[M,128] = relu(A[M,128] @ W[128,128] + b)
// mma.sync.m16n8k8 tf32. CTA = 128 rows, 256 threads (8 warps x 16-row tiles).
// Only W^T staged in smem (PAD=132, conflict-free); A fragments direct from
// global (L2-resident) with cvt.rn.tf32. k-outer loop, acc[16][4] resident.
// ---------------------------------------------------------------------------
#define MMA_SMEM ((128 * PAD + 128) * 4)

__device__ __forceinline__ uint32_t f2tf32(float f) {
    uint32_t r;
    asm("cvt.rn.tf32.f32 %0, %1;" : "=r"(r) : "f"(f));
    return r;
}

__global__ void __launch_bounds__(256, 2) mma_gemm_kernel(
    const float* __restrict__ A, const float* __restrict__ W,
    const float* __restrict__ bias, float* __restrict__ out, int M) {
    extern __shared__ float smf[];
    uint32_t* Ws = (uint32_t*)smf;          // [128][PAD] tf32: Ws[n][k] = tf32(W[k][n])
    float*    bs = smf + 128 * PAD;         // 128

    int tid = threadIdx.x;
    int lane = tid & 31, wid = tid >> 5;
    int row0 = blockIdx.x * 128;

    if (tid < 128) bs[tid] = bias[tid];
    // Stage W^T: coalesced 128B row reads, strided (4-way-conflict) smem writes — cheap, once.
    for (int k = wid; k < 128; k += 8) {
#pragma unroll
        for (int nb = 0; nb < 128; nb += 32) {
            int n = nb + lane;
            Ws[n * PAD + k] = f2tf32(__ldg(&W[k * 128 + n]));
        }
    }
    __syncthreads();

    int g = lane >> 2;   // 0..7
    int i = lane & 3;    // 0..3
    int r0 = row0 + wid * 16 + g;
    int r1 = r0 + 8;
    bool v0 = r0 < M, v1 = r1 < M;
    const float* A0 = A + (size_t)r0 * 128 + i;
    const float* A1 = A + (size_t)r1 * 128 + i;

    float acc[16][4];
#pragma unroll
    for (int nt = 0; nt < 16; nt++)
#pragma unroll
        for (int c = 0; c < 4; c++) acc[nt][c] = 0.f;

#pragma unroll
    for (int kt = 0; kt < 16; kt++) {
        uint32_t a0 = v0 ? f2tf32(__ldg(A0 + kt * 8))     : 0u;
        uint32_t a1 = v1 ? f2tf32(__ldg(A1 + kt * 8))     : 0u;
        uint32_t a2 = v0 ? f2tf32(__ldg(A0 + kt * 8 + 4)) : 0u;
        uint32_t a3 = v1 ? f2tf32(__ldg(A1 + kt * 8 + 4)) : 0u;
#pragma unroll
        for (int nt = 0; nt < 16; nt++) {
            uint32_t b0 = Ws[(nt * 8 + g) * PAD + kt * 8 + i];
            uint32_t b1 = Ws[(nt * 8 + g) * PAD + kt * 8 + i + 4];
            asm volatile(
                "mma.sync.aligned.m16n8k8.row.col.f32.tf32.tf32.f32 "
                "{%0,%1,%2,%3}, {%4,%5,%6,%7}, {%8,%9}, {%0,%1,%2,%3};"
                : "+f"(acc[nt][0]), "+f"(acc[nt][1]), "+f"(acc[nt][2]), "+f"(acc[nt][3])
                : "r"(a0), "r"(a1), "r"(a2), "r"(a3), "r"(b0), "r"(b1));
        }
    }

#pragma unroll
    for (int nt = 0; nt < 16; nt++) {
        int cb = nt * 8 + 2 * i;
        float bx = bs[cb], by = bs[cb + 1];
        if (v0) {
            float2 o;
            o.x = fmaxf(acc[nt][0] + bx, 0.f);
            o.y = fmaxf(acc[nt][1] + by, 0.f);
            *(float2*)(out + (size_t)r0 * 128 + cb) = o;
        }
        if (v1) {
            float2 o;
            o.x = fmaxf(acc[nt][2] + bx, 0.f);
            o.y = fmaxf(acc[nt][3] + by, 0.f);
            *(float2*)(out + (size_t)r1 * 128 + cb) = o;
        }
    }
}

// ---------------------------------------------------------------------------
// gemmP: p[M,2] = A[M,128] @ W3[128,2]   (no bias; warp per row)
// ---------------------------------------------------------------------------
__global__ void gemmP_kernel(const float* __restrict__ A, const float* __restrict__ W3,
                             float* __restrict__ p, int M) {
    int row = (blockIdx.x * blockDim.x + threadIdx.x) >> 5;
    int lane = threadIdx.x & 31;
    if (row >= M) return;
    float s0 = 0.f, s1 = 0.f;
#pragma unroll
    for (int j = 0; j < 4; j++) {
        int k = lane + 32 * j;
        float a = A[(size_t)row * FEAT + k];
        s0 += a * __ldg(&W3[k * 2 + 0]);
        s1 += a * __ldg(&W3[k * 2 + 1]);
    }
#pragma unroll
    for (int o = 16; o; o >>= 1) {
        s0 += __shfl_xor_sync(0xFFFFFFFFu, s0, o);
        s1 += __shfl_xor_sync(0xFFFFFFFFu, s1, o);
    }
    if (lane == 0) {
        p[(size_t)row * 2 + 0] = s0;
        p[(size_t)row * 2 + 1] = s1;
    }
}

// ---------------------------------------------------------------------------
// gatherP: out[i] = p[i] + sum_{j in N(i)} p[j] + b3
// ---------------------------------------------------------------------------
__global__ void gatherP_kernel(const float* __restrict__ p, float* __restrict__ out,
                               const int* __restrict__ off, const int* __restrict__ col,
                               const float* __restrict__ b3, int n_nodes) {
    int node = (blockIdx.x * blockDim.x + threadIdx.x) >> 5;
    int lane = threadIdx.x & 31;
    if (node >= n_nodes) return;
    int k0 = __ldg(&off[node]);
    int k1 = __ldg(&off[node + 1]);
    float a0 = 0.f, a1 = 0.f;
    const float2* p2 = (const float2*)p;
    for (int k = k0 + lane; k < k1; k += 32) {
        int s = __ldg(&col[k]);
        float2 v = p2[s];
        a0 += v.x; a1 += v.y;
    }
#pragma unroll
    for (int o = 16; o; o >>= 1) {
        a0 += __shfl_xor_sync(0xFFFFFFFFu, a0, o);
        a1 += __shfl_xor_sync(0xFFFFFFFFu, a1, o);
    }
    if (lane == 0) {
        float2 self = p2[node];
        out[(size_t)node * 2 + 0] = self.x + a0 + __ldg(&b3[0]);
        out[(size_t)node * 2 + 1] = self.y + a1 + __ldg(&b3[1]);
    }
}

// ---------------------------------------------------------------------------
extern "C" void kernel_launch(void* const* d_in, const int* in_sizes, int n_in,
                              void* d_out, int out_size) {
    const float* x    = (const float*)d_in[0];
    const int*   ei   = (const int*)d_in[1];   // [2, E] int32
    const float* W1   = (const float*)d_in[2];
    const float* b1   = (const float*)d_in[3];
    const float* W2   = (const float*)d_in[4];
    const float* b2   = (const float*)d_in[5];
    const float* W3   = (const float*)d_in[6];
    const float* b3   = (const float*)d_in[7];
    float*       out  = (float*)d_out;

    int n_nodes = in_sizes[0] / FEAT;
    int n_edges = in_sizes[1] / 2;
    const int* esrc = ei;
    const int* edst = ei + n_edges;

    float* bufA;   cudaGetSymbolAddress((void**)&bufA,   g_bufA);
    float* bufB;   cudaGetSymbolAddress((void**)&bufB,   g_bufB);
    float* pbuf;   cudaGetSymbolAddress((void**)&pbuf,   g_p);
    int*   off;    cudaGetSymbolAddress((void**)&off,    g_off);
    int*   cursor; cudaGetSymbolAddress((void**)&cursor, g_cursor);
    int*   col;    cudaGetSymbolAddress((void**)&col,    g_col);
    int*   bsum;   cudaGetSymbolAddress((void**)&bsum,   g_bsum);

    cudaFuncSetAttribute(mma_gemm_kernel, cudaFuncAttributeMaxDynamicSharedMemorySize, MMA_SMEM);

    int edge_blocks = (n_edges + 255) / 256;
    int node_warp_blocks = (n_nodes * 32 + 255) / 256;
    int tc_blocks = (n_nodes + 127) / 128;
    int scan_blocks = (n_nodes + 1023) / 1024;

    // ---- CSR build ----
    cudaMemsetAsync(cursor, 0, n_nodes * sizeof(int));
    hist_kernel<<<edge_blocks, 256>>>(edst, cursor, n_edges);
    scan_block_kernel<<<scan_blocks, 1024>>>(cursor, off, bsum, n_nodes);
    scan_tops_kernel<<<1, 1024>>>(bsum, scan_blocks, off, n_nodes);
    scan_add_kernel<<<scan_blocks, 1024>>>(off, bsum, cursor, n_nodes);
    fill_kernel<<<edge_blocks, 256>>>(esrc, edst, cursor, col, n_edges);

    // ---- Layer 1 ----
    gather128_kernel<<<node_warp_blocks, 256>>>(x, bufA, off, col, n_nodes);
    mma_gemm_kernel<<<tc_blocks, 256, MMA_SMEM>>>(bufA, W1, b1, bufB, n_nodes);

    // ---- Layer 2 ----
    gather128_kernel<<<node_warp_blocks, 256>>>(bufB, bufA, off, col, n_nodes);
    mma_gemm_kernel<<<tc_blocks, 256, MMA_SMEM>>>(bufA, W2, b2, bufB, n_nodes);

    // ---- Layer 3 (project to 2-wide first, aggregate after) ----
    gemmP_kernel<<<node_warp_blocks, 256>>>(bufB, W3, pbuf, n_nodes);
    gatherP_kernel<<<node_warp_blocks, 256>>>(pbuf, out, off, col, b3, n_nodes);
}

// round 8
// speedup vs baseline: 3.5714x; 1.1683x over previous
#include <cuda_runtime.h>
#include <cuda_fp16.h>
#include <cstdint>

#define MAX_NODES 50000
#define MAX_EDGES 1600000
#define FEAT 128
#define PITCH2 68   // W^T smem pitch in half2 words: frag bank = g*4+i -> conflict-free

// Scratch (device globals per harness rules). fp16 node features as ushort.
__device__ __align__(256) unsigned short g_hX[MAX_NODES * FEAT];  // fp16(x)
__device__ __align__(256) unsigned short g_hA[MAX_NODES * FEAT];  // agg (fp16)
__device__ __align__(256) unsigned short g_hB[MAX_NODES * FEAT];  // layer out (fp16)
__device__ __align__(256) float g_p[MAX_NODES * 2];
__device__ int g_off[MAX_NODES + 1];
__device__ int g_cursor[MAX_NODES];
__device__ int g_col[MAX_EDGES];
__device__ int g_bsum[64];

__device__ __forceinline__ uint32_t h2_u32(__half2 h) { return *(uint32_t*)&h; }
__device__ __forceinline__ __half2 u32_h2(uint32_t u) { return *(__half2*)&u; }

// ---------------------------------------------------------------------------
// CSR build
// ---------------------------------------------------------------------------
__global__ void hist_kernel(const int* __restrict__ edst, int* __restrict__ deg, int n_edges) {
    int i = blockIdx.x * blockDim.x + threadIdx.x;
    if (i < n_edges) atomicAdd(&deg[__ldg(&edst[i])], 1);
}

__global__ void scan_block_kernel(const int* __restrict__ counts, int* __restrict__ off,
                                  int* __restrict__ bsum, int n) {
    __shared__ int wtot[32];
    int tid = threadIdx.x, lane = tid & 31, wid = tid >> 5;
    int i = blockIdx.x * 1024 + tid;
    int v = (i < n) ? counts[i] : 0;
    int incl = v;
#pragma unroll
    for (int o = 1; o < 32; o <<= 1) {
        int t = __shfl_up_sync(0xFFFFFFFFu, incl, o);
        if (lane >= o) incl += t;
    }
    if (lane == 31) wtot[wid] = incl;
    __syncthreads();
    if (wid == 0) {
        int w = wtot[lane];
        int wi = w;
#pragma unroll
        for (int o = 1; o < 32; o <<= 1) {
            int t = __shfl_up_sync(0xFFFFFFFFu, wi, o);
            if (lane >= o) wi += t;
        }
        wtot[lane] = wi - w;
        if (lane == 31) bsum[blockIdx.x] = wi;
    }
    __syncthreads();
    if (i < n) off[i] = wtot[wid] + incl - v;
}

__global__ void scan_tops_kernel(int* __restrict__ bsum, int nb, int* __restrict__ off, int n) {
    __shared__ int wtot[32];
    __shared__ int btotal;
    int tid = threadIdx.x, lane = tid & 31, wid = tid >> 5;
    int v = (tid < nb) ? bsum[tid] : 0;
    int incl = v;
#pragma unroll
    for (int o = 1; o < 32; o <<= 1) {
        int t = __shfl_up_sync(0xFFFFFFFFu, incl, o);
        if (lane >= o) incl += t;
    }
    if (lane == 31) wtot[wid] = incl;
    __syncthreads();
    if (wid == 0) {
        int w = wtot[lane];
        int wi = w;
#pragma unroll
        for (int o = 1; o < 32; o <<= 1) {
            int t = __shfl_up_sync(0xFFFFFFFFu, wi, o);
            if (lane >= o) wi += t;
        }
        wtot[lane] = wi - w;
        if (lane == 31) btotal = wi;
    }
    __syncthreads();
    if (tid < nb) bsum[tid] = wtot[wid] + incl - v;
    if (tid == 0) off[n] = btotal;
}

__global__ void scan_add_kernel(int* __restrict__ off, const int* __restrict__ bsum,
                                int* __restrict__ cursor, int n) {
    int i = blockIdx.x * 1024 + threadIdx.x;
    if (i < n) {
        int v = off[i] + bsum[blockIdx.x];
        off[i] = v;
        cursor[i] = v;
    }
}

__global__ void fill_kernel(const int* __restrict__ esrc, const int* __restrict__ edst,
                            int* __restrict__ cursor, int* __restrict__ col, int n_edges) {
    int i = blockIdx.x * blockDim.x + threadIdx.x;
    if (i < n_edges) {
        int d = __ldg(&edst[i]);
        int pos = atomicAdd(&cursor[d], 1);
        col[pos] = __ldg(&esrc[i]);
    }
}

// ---------------------------------------------------------------------------
// cvt: fp32 -> fp16 (x once per call)
// ---------------------------------------------------------------------------
__global__ void cvt_h_kernel(const float* __restrict__ x, unsigned short* __restrict__ xh, int n4) {
    int i = blockIdx.x * blockDim.x + threadIdx.x;
    if (i < n4) {
        float4 v = ((const float4*)x)[i];
        __half2 h0 = __floats2half2_rn(v.x, v.y);
        __half2 h1 = __floats2half2_rn(v.z, v.w);
        ((uint2*)xh)[i] = make_uint2(h2_u32(h0), h2_u32(h1));
    }
}

// ---------------------------------------------------------------------------
// gather_h: agg[i] = x[i] + sum_{j in N(i)} x[j]  (fp16 storage, fp32 accum)
// warp per node; lane handles 4 halves (8B) -> 256B/row
// ---------------------------------------------------------------------------
__global__ void gather_h_kernel(const unsigned short* __restrict__ x,
                                unsigned short* __restrict__ agg,
                                const int* __restrict__ off, const int* __restrict__ col,
                                int n_nodes) {
    int node = (blockIdx.x * blockDim.x + threadIdx.x) >> 5;
    int lane = threadIdx.x & 31;
    if (node >= n_nodes) return;
    int k  = __ldg(&off[node]);
    int k1 = __ldg(&off[node + 1]);
    const uint2* x2 = (const uint2*)x;   // 4 halves per uint2; 32 per row

    uint2 s = x2[(size_t)node * 32 + lane];
    float2 f0 = __half22float2(u32_h2(s.x));
    float2 f1 = __half22float2(u32_h2(s.y));
    float4 acc = make_float4(f0.x, f0.y, f1.x, f1.y);

    int nxt = (k < k1) ? __ldg(&col[k]) : 0;
    while (k < k1) {
        int srci = nxt;
        k++;
        if (k < k1) nxt = __ldg(&col[k]);
        uint2 v = x2[(size_t)srci * 32 + lane];
        float2 a = __half22float2(u32_h2(v.x));
        float2 b = __half22float2(u32_h2(v.y));
        acc.x += a.x; acc.y += a.y; acc.z += b.x; acc.w += b.y;
    }
    __half2 o0 = __floats2half2_rn(acc.x, acc.y);
    __half2 o1 = __floats2half2_rn(acc.z, acc.w);
    ((uint2*)agg)[(size_t)node * 32 + lane] = make_uint2(h2_u32(o0), h2_u32(o1));
}

// ---------------------------------------------------------------------------
// mma_gemm_h: outh[M,128] = fp16(relu(Ah[M,128] @ W[128,128] + b))
// mma.sync.m16n8k16 f16 (fp32 accum). CTA=128 rows, 256 thr (8 warps x 16 rows).
// W^T staged fp16 in smem [n][k2] pitch PITCH2; A frags direct from global fp16.
// ---------------------------------------------------------------------------
#define MMAH_SMEM (128 * PITCH2 * 4 + 128 * 4)

__global__ void __launch_bounds__(256, 2) mma_gemm_h_kernel(
    const unsigned short* __restrict__ Ah, const float* __restrict__ W,
    const float* __restrict__ bias, unsigned short* __restrict__ outh, int M) {
    extern __shared__ float smf[];
    uint32_t* Wh2 = (uint32_t*)smf;          // [128][PITCH2] half2: (W[2k2][n], W[2k2+1][n])
    float*    bs  = smf + 128 * PITCH2;      // 128

    int tid = threadIdx.x;
    int lane = tid & 31, wid = tid >> 5;
    int row0 = blockIdx.x * 128;

    if (tid < 128) bs[tid] = bias[tid];
    // Stage W^T as half2: idx -> (n = idx&127, k2 = idx>>7); coalesced global reads
    for (int idx = tid; idx < 128 * 64; idx += 256) {
        int n = idx & 127, k2 = idx >> 7;
        float w0 = __ldg(&W[(2 * k2) * 128 + n]);
        float w1 = __ldg(&W[(2 * k2 + 1) * 128 + n]);
        __half2 h = __floats2half2_rn(w0, w1);
        Wh2[n * PITCH2 + k2] = h2_u32(h);
    }
    __syncthreads();

    int g = lane >> 2;   // 0..7
    int i = lane & 3;    // 0..3
    int r0 = row0 + wid * 16 + g;
    int r1 = r0 + 8;
    bool v0 = r0 < M, v1 = r1 < M;
    // half2 view of A rows: 64 half2 per row
    const uint32_t* A0 = (const uint32_t*)Ah + (size_t)r0 * 64 + i;
    const uint32_t* A1 = (const uint32_t*)Ah + (size_t)r1 * 64 + i;

    float acc[16][4];
#pragma unroll
    for (int nt = 0; nt < 16; nt++)
#pragma unroll
        for (int c = 0; c < 4; c++) acc[nt][c] = 0.f;

#pragma unroll
    for (int kt = 0; kt < 8; kt++) {
        // A fragment (m16n8k16 row): a0=(g, 2i..) a1=(g+8, 2i..) a2=(g, 2i+8..) a3=(g+8, 2i+8..)
        uint32_t a0 = v0 ? __ldg(A0 + kt * 8)     : 0u;
        uint32_t a1 = v1 ? __ldg(A1 + kt * 8)     : 0u;
        uint32_t a2 = v0 ? __ldg(A0 + kt * 8 + 4) : 0u;
        uint32_t a3 = v1 ? __ldg(A1 + kt * 8 + 4) : 0u;
#pragma unroll
        for (int nt = 0; nt < 16; nt++) {
            int n = nt * 8 + g;
            uint32_t b0 = Wh2[n * PITCH2 + kt * 8 + i];
            uint32_t b1 = Wh2[n * PITCH2 + kt * 8 + i + 4];
            asm volatile(
                "mma.sync.aligned.m16n8k16.row.col.f32.f16.f16.f32 "
                "{%0,%1,%2,%3}, {%4,%5,%6,%7}, {%8,%9}, {%0,%1,%2,%3};"
                : "+f"(acc[nt][0]), "+f"(acc[nt][1]), "+f"(acc[nt][2]), "+f"(acc[nt][3])
                : "r"(a0), "r"(a1), "r"(a2), "r"(a3), "r"(b0), "r"(b1));
        }
    }

#pragma unroll
    for (int nt = 0; nt < 16; nt++) {
        int cb = nt * 8 + 2 * i;
        float bx = bs[cb], by = bs[cb + 1];
        if (v0) {
            __half2 o = __floats2half2_rn(fmaxf(acc[nt][0] + bx, 0.f),
                                          fmaxf(acc[nt][1] + by, 0.f));
            ((uint32_t*)outh)[(size_t)r0 * 64 + nt * 4 + i] = h2_u32(o);
        }
        if (v1) {
            __half2 o = __floats2half2_rn(fmaxf(acc[nt][2] + bx, 0.f),
                                          fmaxf(acc[nt][3] + by, 0.f));
            ((uint32_t*)outh)[(size_t)r1 * 64 + nt * 4 + i] = h2_u32(o);
        }
    }
}

// ---------------------------------------------------------------------------
// gemmP: p[M,2] = Ah[M,128] @ W3[128,2]   (fp16 A; no bias; warp per row)
// ---------------------------------------------------------------------------
__global__ void gemmP_kernel(const unsigned short* __restrict__ Ah, const float* __restrict__ W3,
                             float* __restrict__ p, int M) {
    int row = (blockIdx.x * blockDim.x + threadIdx.x) >> 5;
    int lane = threadIdx.x & 31;
    if (row >= M) return;
    const uint32_t* A2 = (const uint32_t*)Ah;
    float s0 = 0.f, s1 = 0.f;
#pragma unroll
    for (int j = 0; j < 2; j++) {
        int h2 = lane + 32 * j;               // half2 index: k = 2*h2, 2*h2+1
        uint32_t u = A2[(size_t)row * 64 + h2];
        float2 f = __half22float2(u32_h2(u));
        int k = 2 * h2;
        s0 += f.x * __ldg(&W3[k * 2 + 0]) + f.y * __ldg(&W3[(k + 1) * 2 + 0]);
        s1 += f.x * __ldg(&W3[k * 2 + 1]) + f.y * __ldg(&W3[(k + 1) * 2 + 1]);
    }
#pragma unroll
    for (int o = 16; o; o >>= 1) {
        s0 += __shfl_xor_sync(0xFFFFFFFFu, s0, o);
        s1 += __shfl_xor_sync(0xFFFFFFFFu, s1, o);
    }
    if (lane == 0) {
        p[(size_t)row * 2 + 0] = s0;
        p[(size_t)row * 2 + 1] = s1;
    }
}

// ---------------------------------------------------------------------------
// gatherP: out[i] = p[i] + sum_{j in N(i)} p[j] + b3   (fp32)
// ---------------------------------------------------------------------------
__global__ void gatherP_kernel(const float* __restrict__ p, float* __restrict__ out,
                               const int* __restrict__ off, const int* __restrict__ col,
                               const float* __restrict__ b3, int n_nodes) {
    int node = (blockIdx.x * blockDim.x + threadIdx.x) >> 5;
    int lane = threadIdx.x & 31;
    if (node >= n_nodes) return;
    int k0 = __ldg(&off[node]);
    int k1 = __ldg(&off[node + 1]);
    float a0 = 0.f, a1 = 0.f;
    const float2* p2 = (const float2*)p;
    for (int k = k0 + lane; k < k1; k += 32) {
        int s = __ldg(&col[k]);
        float2 v = p2[s];
        a0 += v.x; a1 += v.y;
    }
#pragma unroll
    for (int o = 16; o; o >>= 1) {
        a0 += __shfl_xor_sync(0xFFFFFFFFu, a0, o);
        a1 += __shfl_xor_sync(0xFFFFFFFFu, a1, o);
    }
    if (lane == 0) {
        float2 self = p2[node];
        out[(size_t)node * 2 + 0] = self.x + a0 + __ldg(&b3[0]);
        out[(size_t)node * 2 + 1] = self.y + a1 + __ldg(&b3[1]);
    }
}

// ---------------------------------------------------------------------------
extern "C" void kernel_launch(void* const* d_in, const int* in_sizes, int n_in,
                              void* d_out, int out_size) {
    const float* x    = (const float*)d_in[0];
    const int*   ei   = (const int*)d_in[1];   // [2, E] int32
    const float* W1   = (const float*)d_in[2];
    const float* b1   = (const float*)d_in[3];
    const float* W2   = (const float*)d_in[4];
    const float* b2   = (const float*)d_in[5];
    const float* W3   = (const float*)d_in[6];
    const float* b3   = (const float*)d_in[7];
    float*       out  = (float*)d_out;

    int n_nodes = in_sizes[0] / FEAT;
    int n_edges = in_sizes[1] / 2;
    const int* esrc = ei;
    const int* edst = ei + n_edges;

    unsigned short* hX; cudaGetSymbolAddress((void**)&hX, g_hX);
    unsigned short* hA; cudaGetSymbolAddress((void**)&hA, g_hA);
    unsigned short* hB; cudaGetSymbolAddress((void**)&hB, g_hB);
    float* pbuf;   cudaGetSymbolAddress((void**)&pbuf,   g_p);
    int*   off;    cudaGetSymbolAddress((void**)&off,    g_off);
    int*   cursor; cudaGetSymbolAddress((void**)&cursor, g_cursor);
    int*   col;    cudaGetSymbolAddress((void**)&col,    g_col);
    int*   bsum;   cudaGetSymbolAddress((void**)&bsum,   g_bsum);

    cudaFuncSetAttribute(mma_gemm_h_kernel, cudaFuncAttributeMaxDynamicSharedMemorySize, MMAH_SMEM);

    int edge_blocks = (n_edges + 255) / 256;
    int node_warp_blocks = (n_nodes * 32 + 255) / 256;
    int tc_blocks = (n_nodes + 127) / 128;
    int scan_blocks = (n_nodes + 1023) / 1024;
    int n4 = n_nodes * FEAT / 4;

    // ---- CSR build ----
    cudaMemsetAsync(cursor, 0, n_nodes * sizeof(int));
    hist_kernel<<<edge_blocks, 256>>>(edst, cursor, n_edges);
    scan_block_kernel<<<scan_blocks, 1024>>>(cursor, off, bsum, n_nodes);
    scan_tops_kernel<<<1, 1024>>>(bsum, scan_blocks, off, n_nodes);
    scan_add_kernel<<<scan_blocks, 1024>>>(off, bsum, cursor, n_nodes);
    fill_kernel<<<edge_blocks, 256>>>(esrc, edst, cursor, col, n_edges);

    // ---- x -> fp16 ----
    cvt_h_kernel<<<(n4 + 255) / 256, 256>>>(x, hX, n4);

    // ---- Layer 1 ----
    gather_h_kernel<<<node_warp_blocks, 256>>>(hX, hA, off, col, n_nodes);
    mma_gemm_h_kernel<<<tc_blocks, 256, MMAH_SMEM>>>(hA, W1, b1, hB, n_nodes);

    // ---- Layer 2 ----
    gather_h_kernel<<<node_warp_blocks, 256>>>(hB, hA, off, col, n_nodes);
    mma_gemm_h_kernel<<<tc_blocks, 256, MMAH_SMEM>>>(hA, W2, b2, hB, n_nodes);

    // ---- Layer 3 (project to 2-wide first, aggregate after) ----
    gemmP_kernel<<<node_warp_blocks, 256>>>(hB, W3, pbuf, n_nodes);
    gatherP_kernel<<<node_warp_blocks, 256>>>(pbuf, out, off, col, b3, n_nodes);
}